// round 1
// baseline (speedup 1.0000x reference)
#include <cuda_runtime.h>
#include <cuda_bf16.h>

// ---------------------------------------------------------------------------
// Octree sparse-conv pipeline, 5 stages of gather-GEMM + BatchNorm(batch
// stats) + ReLU.  Sizes are compile-time constants from the reference.
// ---------------------------------------------------------------------------

#define N0_ 262144
#define N1_ 32768
#define N2_ 4096
#define EPS_ 1e-5f

// Scratch (static device memory; allocation APIs are forbidden)
__device__ float g_y0[N0_ * 24];
__device__ float g_y1[N1_ * 48];
__device__ float g_y2[N1_ * 48];
__device__ float g_y3[N2_ * 96];
__device__ float g_y4[N2_ * 96];
__device__ float g_psum[1024 * 96];
__device__ float g_psq [1024 * 96];
__device__ float g_scale[5 * 96];
__device__ float g_shift[5 * 96];

// ---------------------------------------------------------------------------
// Generic gather-conv stage.
//   y[m, dofs+j] = sum_k sum_c act(x[neigh[m,k], c]) * W[k, c, dofs+j]
// where act() applies the previous stage's BN scale/shift + ReLU (NORM_IN).
// One thread computes one row and DTILE output channels. Weights are staged
// through shared memory in K-chunks. Each block also emits per-block partial
// sum / sum-of-squares for its channel slice (deterministic reduction).
// Block = 256 threads; M must be a multiple of 256 (true for all stages).
// grid.x = M/256 row blocks, grid.y = COUT/DTILE channel tiles.
// ---------------------------------------------------------------------------
template<int K, int CIN, int COUT, int DTILE, int KCHUNK, bool NORM_IN>
__global__ void __launch_bounds__(256)
conv_stage(const float* __restrict__ xin,
           const int*   __restrict__ neigh,
           const float* __restrict__ W,       // [K, CIN, COUT]
           const float* __restrict__ nscale,  // [CIN] (NORM_IN only)
           const float* __restrict__ nshift,  // [CIN]
           float* __restrict__ yout,          // [M, COUT]
           float* __restrict__ psum,          // [gridDim.x * COUT]
           float* __restrict__ psq)
{
    constexpr int NCHUNKS = (K + KCHUNK - 1) / KCHUNK;

    __shared__ float sW[KCHUNK * CIN * DTILE];
    __shared__ float sScale[NORM_IN ? CIN : 1];
    __shared__ float sShift[NORM_IN ? CIN : 1];
    __shared__ float sRed[8][DTILE][2];

    const int tid     = threadIdx.x;
    const int dofs    = blockIdx.y * DTILE;
    const int rowBase = blockIdx.x * 256;
    const int row     = rowBase + tid;

    if (NORM_IN) {
        for (int c = tid; c < CIN; c += 256) {
            sScale[c] = nscale[c];
            sShift[c] = nshift[c];
        }
    }

    float acc[DTILE];
#pragma unroll
    for (int j = 0; j < DTILE; j++) acc[j] = 0.f;

    for (int ch = 0; ch < NCHUNKS; ch++) {
        const int k0 = ch * KCHUNK;
        __syncthreads();
        // Cooperative load of the W chunk: [KCHUNK][CIN][DTILE], d innermost
        // (coalesced: consecutive i -> consecutive d in global W).
        for (int i = tid; i < KCHUNK * CIN * DTILE; i += 256) {
            const int j   = i % DTILE;
            const int rem = i / DTILE;
            const int c   = rem % CIN;
            const int k   = rem / CIN;
            sW[i] = W[((long)(k0 + k) * CIN + c) * COUT + dofs + j];
        }
        __syncthreads();

        // Neighbor indices for this chunk (L1-cached; cheap vs FMA count)
        int idxs[KCHUNK];
#pragma unroll
        for (int k = 0; k < KCHUNK; k++)
            idxs[k] = neigh[(long)row * K + k0 + k];

#pragma unroll 1
        for (int k = 0; k < KCHUNK; k++) {
            const float* __restrict__ xr = xin + (long)idxs[k] * CIN;
            const float* __restrict__ wr = &sW[k * CIN * DTILE];

            if (CIN % 4 == 0) {
                const float4* __restrict__ xr4 = reinterpret_cast<const float4*>(xr);
#pragma unroll
                for (int c4 = 0; c4 < CIN / 4; c4++) {
                    float4 xv = xr4[c4];
                    if (NORM_IN) {
                        xv.x = fmaxf(fmaf(xv.x, sScale[c4*4+0], sShift[c4*4+0]), 0.f);
                        xv.y = fmaxf(fmaf(xv.y, sScale[c4*4+1], sShift[c4*4+1]), 0.f);
                        xv.z = fmaxf(fmaf(xv.z, sScale[c4*4+2], sShift[c4*4+2]), 0.f);
                        xv.w = fmaxf(fmaf(xv.w, sScale[c4*4+3], sShift[c4*4+3]), 0.f);
                    }
                    const float v[4] = {xv.x, xv.y, xv.z, xv.w};
#pragma unroll
                    for (int u = 0; u < 4; u++) {
                        const float* wrow = wr + (c4 * 4 + u) * DTILE;
#pragma unroll
                        for (int j = 0; j < DTILE; j += 4) {
                            float4 w4 = *reinterpret_cast<const float4*>(wrow + j);
                            acc[j+0] = fmaf(v[u], w4.x, acc[j+0]);
                            acc[j+1] = fmaf(v[u], w4.y, acc[j+1]);
                            acc[j+2] = fmaf(v[u], w4.z, acc[j+2]);
                            acc[j+3] = fmaf(v[u], w4.w, acc[j+3]);
                        }
                    }
                }
            } else {
#pragma unroll
                for (int c = 0; c < CIN; c++) {
                    float xv = xr[c];
                    if (NORM_IN) xv = fmaxf(fmaf(xv, sScale[c], sShift[c]), 0.f);
                    const float* wrow = wr + c * DTILE;
#pragma unroll
                    for (int j = 0; j < DTILE; j += 4) {
                        float4 w4 = *reinterpret_cast<const float4*>(wrow + j);
                        acc[j+0] = fmaf(xv, w4.x, acc[j+0]);
                        acc[j+1] = fmaf(xv, w4.y, acc[j+1]);
                        acc[j+2] = fmaf(xv, w4.z, acc[j+2]);
                        acc[j+3] = fmaf(xv, w4.w, acc[j+3]);
                    }
                }
            }
        }
    }

    // Write raw (pre-BN) outputs
#pragma unroll
    for (int j = 0; j < DTILE; j++)
        yout[(long)row * COUT + dofs + j] = acc[j];

    // Deterministic block reduction of sum / sumsq per channel
    const int lane = tid & 31;
    const int warp = tid >> 5;
#pragma unroll
    for (int j = 0; j < DTILE; j++) {
        float s = acc[j];
        float q = acc[j] * acc[j];
#pragma unroll
        for (int off = 16; off > 0; off >>= 1) {
            s += __shfl_down_sync(0xFFFFFFFFu, s, off);
            q += __shfl_down_sync(0xFFFFFFFFu, q, off);
        }
        if (lane == 0) { sRed[warp][j][0] = s; sRed[warp][j][1] = q; }
    }
    __syncthreads();
    if (tid < DTILE) {
        float s = 0.f, q = 0.f;
#pragma unroll
        for (int w = 0; w < 8; w++) { s += sRed[w][tid][0]; q += sRed[w][tid][1]; }
        psum[(long)blockIdx.x * COUT + dofs + tid] = s;
        psq [(long)blockIdx.x * COUT + dofs + tid] = q;
    }
}

// ---------------------------------------------------------------------------
// Per-channel BN finalize: reduce block partials -> scale/shift.
// grid = COUT blocks, 256 threads. Deterministic tree reduction.
// ---------------------------------------------------------------------------
__global__ void bn_finalize(const float* __restrict__ psum,
                            const float* __restrict__ psq,
                            const float* __restrict__ gamma,
                            const float* __restrict__ beta,
                            float* __restrict__ scale,
                            float* __restrict__ shift,
                            int nRB, int cout, float invM)
{
    __shared__ float ss[256], sq[256];
    const int d = blockIdx.x;
    const int t = threadIdx.x;
    float s = 0.f, q = 0.f;
    for (int b = t; b < nRB; b += 256) {
        s += psum[(long)b * cout + d];
        q += psq [(long)b * cout + d];
    }
    ss[t] = s; sq[t] = q;
    __syncthreads();
    for (int o = 128; o > 0; o >>= 1) {
        if (t < o) { ss[t] += ss[t + o]; sq[t] += sq[t + o]; }
        __syncthreads();
    }
    if (t == 0) {
        const float mean = ss[0] * invM;
        const float var  = sq[0] * invM - mean * mean;
        const float sc   = gamma[d] * rsqrtf(var + EPS_);
        scale[d] = sc;
        shift[d] = beta[d] - mean * sc;
    }
}

// Final elementwise BN + ReLU into d_out
__global__ void final_norm(const float* __restrict__ y,
                           const float* __restrict__ scale,
                           const float* __restrict__ shift,
                           float* __restrict__ out, int total, int cout)
{
    const int i = blockIdx.x * 256 + threadIdx.x;
    if (i < total) {
        const int d = i % cout;
        out[i] = fmaxf(fmaf(y[i], scale[d], shift[d]), 0.f);
    }
}

// ---------------------------------------------------------------------------
extern "C" void kernel_launch(void* const* d_in, const int* in_sizes, int n_in,
                              void* d_out, int out_size)
{
    const float* data   = (const float*)d_in[0];
    const int*   neigh0 = (const int*)  d_in[1];
    const int*   child0 = (const int*)  d_in[2];
    const int*   neigh1 = (const int*)  d_in[3];
    const int*   child1 = (const int*)  d_in[4];
    const int*   neigh2 = (const int*)  d_in[5];
    const float* w0  = (const float*)d_in[6];
    const float* g0  = (const float*)d_in[7];
    const float* b0  = (const float*)d_in[8];
    const float* wd0 = (const float*)d_in[9];
    const float* gd0 = (const float*)d_in[10];
    const float* bd0 = (const float*)d_in[11];
    const float* w1  = (const float*)d_in[12];
    const float* g1  = (const float*)d_in[13];
    const float* b1  = (const float*)d_in[14];
    const float* wd1 = (const float*)d_in[15];
    const float* gd1 = (const float*)d_in[16];
    const float* bd1 = (const float*)d_in[17];
    const float* wp  = (const float*)d_in[18];
    const float* gp  = (const float*)d_in[19];
    const float* bp  = (const float*)d_in[20];

    float *y0, *y1, *y2, *y3, *y4, *psum, *psq, *scl, *shf;
    cudaGetSymbolAddress((void**)&y0,   g_y0);
    cudaGetSymbolAddress((void**)&y1,   g_y1);
    cudaGetSymbolAddress((void**)&y2,   g_y2);
    cudaGetSymbolAddress((void**)&y3,   g_y3);
    cudaGetSymbolAddress((void**)&y4,   g_y4);
    cudaGetSymbolAddress((void**)&psum, g_psum);
    cudaGetSymbolAddress((void**)&psq,  g_psq);
    cudaGetSymbolAddress((void**)&scl,  g_scale);
    cudaGetSymbolAddress((void**)&shf,  g_shift);

    // Stage A: data[N0,3] x w0[27,3,24] -> y0[N0,24]
    conv_stage<27, 3, 24, 24, 27, false><<<dim3(N0_/256, 1), 256>>>(
        data, neigh0, w0, nullptr, nullptr, y0, psum, psq);
    bn_finalize<<<24, 256>>>(psum, psq, g0, b0, scl + 0, shf + 0,
                             N0_/256, 24, 1.f / N0_);

    // Stage B: y0 (normed) x wd0[8,24,48] -> y1[N1,48]
    conv_stage<8, 24, 48, 24, 8, true><<<dim3(N1_/256, 2), 256>>>(
        y0, child0, wd0, scl + 0, shf + 0, y1, psum, psq);
    bn_finalize<<<48, 256>>>(psum, psq, gd0, bd0, scl + 96, shf + 96,
                             N1_/256, 48, 1.f / N1_);

    // Stage C: y1 (normed) x w1[27,48,48] -> y2[N1,48]
    conv_stage<27, 48, 48, 24, 9, true><<<dim3(N1_/256, 2), 256>>>(
        y1, neigh1, w1, scl + 96, shf + 96, y2, psum, psq);
    bn_finalize<<<48, 256>>>(psum, psq, g1, b1, scl + 192, shf + 192,
                             N1_/256, 48, 1.f / N1_);

    // Stage D: y2 (normed) x wd1[8,48,96] -> y3[N2,96]
    conv_stage<8, 48, 96, 12, 8, true><<<dim3(N2_/256, 8), 256>>>(
        y2, child1, wd1, scl + 192, shf + 192, y3, psum, psq);
    bn_finalize<<<96, 256>>>(psum, psq, gd1, bd1, scl + 288, shf + 288,
                             N2_/256, 96, 1.f / N2_);

    // Stage E: y3 (normed) x wp[27,96,96] -> y4[N2,96]
    conv_stage<27, 96, 96, 12, 9, true><<<dim3(N2_/256, 8), 256>>>(
        y3, neigh2, wp, scl + 288, shf + 288, y4, psum, psq);
    bn_finalize<<<96, 256>>>(psum, psq, gp, bp, scl + 384, shf + 384,
                             N2_/256, 96, 1.f / N2_);

    // Final BN + ReLU -> d_out [N2, 96]
    final_norm<<<(N2_ * 96 + 255) / 256, 256>>>(
        y4, scl + 384, shf + 384, (float*)d_out, N2_ * 96, 96);
}